// round 13
// baseline (speedup 1.0000x reference)
#include <cuda_runtime.h>

// ---------------- problem constants ----------------
#define NB      4096
#define NNOTES  48
#define NF      256
#define NU      256
#define NG      1024      // 4 * NU (i,f,g,o), interleaved [unit][gate]
#define K0TOT   520       // ih0 (259) + pad(1) + hh0 (256) + pad(4)  -> 65 chunks
#define K1TOT   512       // ih1 (256) + hh1 (256)                    -> 64 chunks
#define KC      8         // K rows per pipeline chunk
#define NSTAGE  3
#define MROWS   32        // batch rows per CTA
#define NTHR    1024
#define ASTR    36        // transposed-A row stride (32 rows + 4 pad)

typedef unsigned long long u64;

// ---------------- device scratch (static, allocation-guard-safe) ----------------
__device__ __align__(16) float g_W0[K0TOT * NG];   // [k][unit*4+gate], pad rows zero
__device__ __align__(16) float g_W1[K1TOT * NG];   // [k][unit*4+gate]
__device__ __align__(16) float g_b0[NG];           // [unit*4+gate]
__device__ __align__(16) float g_b1[NG];
// c scratch, kernel-private layout: [cta][ug][rp*8 + rg*2 + j]
__device__ __align__(16) float g_c0[NB * NU];
__device__ __align__(16) float g_c1[NB * NU];

// ---------------- helpers ----------------
__device__ __forceinline__ u64 pack2(float x) {
    u64 r;
    asm("mov.b64 %0, {%1, %1};" : "=l"(r) : "r"(__float_as_uint(x)));
    return r;
}
__device__ __forceinline__ void fma2(u64& acc, u64 a, u64 b) {
    asm("fma.rn.f32x2 %0, %1, %2, %0;" : "+l"(acc) : "l"(a), "l"(b));
}
__device__ __forceinline__ void unpack2(u64 v, float& lo, float& hi) {
    unsigned int a, b;
    asm("mov.b64 {%0, %1}, %2;" : "=r"(a), "=r"(b) : "l"(v));
    lo = __uint_as_float(a);
    hi = __uint_as_float(b);
}
__device__ __forceinline__ float sigf(float x) {
    return 1.0f / (1.0f + expf(-x));
}
__device__ __forceinline__ void cp16(unsigned dst, const float* src) {
    asm volatile("cp.async.ca.shared.global [%0], [%1], 16;" :: "r"(dst), "l"(src) : "memory");
}
__device__ __forceinline__ void cp_commit() {
    asm volatile("cp.async.commit_group;" ::: "memory");
}
__device__ __forceinline__ void cp_wait1() {
    asm volatile("cp.async.wait_group 1;" ::: "memory");
}

// ---------------- prep: transpose + interleave + concatenate weights ----------------
__global__ void prep_kernel(const float* __restrict__ W_ih0, const float* __restrict__ W_hh0,
                            const float* __restrict__ b_ih0, const float* __restrict__ b_hh0,
                            const float* __restrict__ W_ih1, const float* __restrict__ W_hh1,
                            const float* __restrict__ b_ih1, const float* __restrict__ b_hh1) {
    int tid = blockIdx.x * blockDim.x + threadIdx.x;
    int stride = gridDim.x * blockDim.x;
    for (int i = tid; i < K0TOT * NG; i += stride) {
        int k = i >> 10, j = i & 1023;
        int u = j >> 2, g = j & 3;
        int orow = g * 256 + u;              // original row in [4*NU, K] weight
        float v = 0.f;
        if (k < 259)                  v = W_ih0[orow * 259 + k];
        else if (k >= 260 && k < 516) v = W_hh0[orow * 256 + (k - 260)];
        g_W0[i] = v;                          // rows 259, 516..519 stay zero
    }
    for (int i = tid; i < K1TOT * NG; i += stride) {
        int k = i >> 10, j = i & 1023;
        int u = j >> 2, g = j & 3;
        int orow = g * 256 + u;
        g_W1[i] = (k < 256) ? W_ih1[orow * 256 + k] : W_hh1[orow * 256 + (k - 256)];
    }
    for (int i = tid; i < NG; i += stride) {
        int u = i >> 2, g = i & 3;
        int orow = g * 256 + u;
        g_b0[i] = b_ih0[orow] + b_hh0[orow];
        g_b1[i] = b_ih1[orow] + b_hh1[orow];
    }
}

// ---------------- GEMM over one layer (contiguous concatenated A) ----------------
// Warp remap: rg = tid&3, ug = tid>>2 -> the 4 row-group replicas of a unit sit in
// the SAME warp, so their identical W addresses merge into one broadcast wavefront
// (W: 1 wf/warp/kk instead of 4). A loads: 4 distinct 16B per warp -> ~1.5 wf.
// Race-free 3-stage cp.async pipeline: wait -> barrier -> issue (into the buffer
// freed by the barrier) -> compute.
__device__ __forceinline__ void gemm_layer(
    u64 (&acc)[4][4],
    const float* A,                      // contiguous [ktot][ASTR]
    const float* __restrict__ Wg, int nchunks,
    const float* sh_w, unsigned sw_u32, int tid, int rg8, int ug)
{
    // prologue: stage chunks 0 and 1 (2048 float4 per chunk, 2 per thread)
#pragma unroll
    for (int p = 0; p < 2; p++) {
        unsigned d = sw_u32 + (unsigned)(p * (KC * NG) + tid * 4) * 4u;
        const float* s = Wg + p * (KC * NG) + tid * 4;
        cp16(d, s);
        cp16(d + 1024 * 16, s + 1024 * 4);
        cp_commit();
    }
    int stage = 0, stage2 = 2;   // buffer of chunk ci, and of chunk ci+2
    for (int ci = 0; ci < nchunks; ci++) {
        cp_wait1();              // chunk ci complete for THIS thread (most recent
                                 // committed group is ci+1; all older are done)
        __syncthreads();         // all threads' chunk-ci copies visible; buffer
                                 // stage2 (last read at chunk ci-1) is now free
        if (ci + 2 < nchunks) {  // issue AFTER the barrier -> no read/write race
            unsigned d = sw_u32 + (unsigned)(stage2 * (KC * NG) + tid * 4) * 4u;
            const float* s = Wg + (size_t)(ci + 2) * (KC * NG) + tid * 4;
            cp16(d, s);
            cp16(d + 1024 * 16, s + 1024 * 4);
        }
        cp_commit();             // commit every iter (keeps group positions fixed)

        const float* wb = sh_w + stage * (KC * NG) + ug * 4;
        const float* ab = A + ci * (KC * ASTR) + rg8;
#pragma unroll
        for (int kk = 0; kk < KC; kk++) {
            ulonglong2 av0 = *(const ulonglong2*)(ab + kk * ASTR);      // rows 0-3
            ulonglong2 av1 = *(const ulonglong2*)(ab + kk * ASTR + 4);  // rows 4-7
            float4 w4 = *(const float4*)(wb + kk * NG);    // gates i,f,g,o (bcast x4)
            u64 wi = pack2(w4.x);
            u64 wf = pack2(w4.y);
            u64 wg = pack2(w4.z);
            u64 wo = pack2(w4.w);
            fma2(acc[0][0], av0.x, wi); fma2(acc[1][0], av0.y, wi);
            fma2(acc[2][0], av1.x, wi); fma2(acc[3][0], av1.y, wi);
            fma2(acc[0][1], av0.x, wf); fma2(acc[1][1], av0.y, wf);
            fma2(acc[2][1], av1.x, wf); fma2(acc[3][1], av1.y, wf);
            fma2(acc[0][2], av0.x, wg); fma2(acc[1][2], av0.y, wg);
            fma2(acc[2][2], av1.x, wg); fma2(acc[3][2], av1.y, wg);
            fma2(acc[0][3], av0.x, wo); fma2(acc[1][3], av0.y, wo);
            fma2(acc[2][3], av1.x, wo); fma2(acc[3][3], av1.y, wo);
        }
        stage  = stage  + 1; if (stage  == NSTAGE) stage  = 0;
        stage2 = stage2 + 1; if (stage2 == NSTAGE) stage2 = 0;
    }
}

// ---------------- LSTM cell elementwise ----------------
// Thread owns rows rg8..rg8+7 (4 lane-pairs) and unit ug.
// c scratch layout [ug*32 + rp*8 + rg*2 + j]: warp ops land on clean 32B sectors.
__device__ __forceinline__ void cell_update(
    u64 (&acc)[4][4], const float2 (&cin)[4], float* __restrict__ cg,
    float* hT, int rg8, int rg, int ug)
{
    float hn[8];
#pragma unroll
    for (int rp = 0; rp < 4; rp++) {
        float i0, i1, f0, f1, g0, g1, o0, o1;
        unpack2(acc[rp][0], i0, i1);
        unpack2(acc[rp][1], f0, f1);
        unpack2(acc[rp][2], g0, g1);
        unpack2(acc[rp][3], o0, o1);
        float cn0 = sigf(f0) * cin[rp].x + sigf(i0) * tanhf(g0);
        float cn1 = sigf(f1) * cin[rp].y + sigf(i1) * tanhf(g1);
        *(float2*)(cg + ug * 32 + rp * 8 + rg * 2) = make_float2(cn0, cn1);
        hn[2 * rp]     = sigf(o0) * tanhf(cn0);
        hn[2 * rp + 1] = sigf(o1) * tanhf(cn1);
    }
    __syncthreads();   // all GEMM readers of old hT are done
    float4* d = (float4*)(hT + ug * ASTR + rg8);
    d[0] = make_float4(hn[0], hn[1], hn[2], hn[3]);
    d[1] = make_float4(hn[4], hn[5], hn[6], hn[7]);
    __syncthreads();   // new hT visible (output head / next GEMM)
}

// ---------------- main persistent kernel ----------------
__global__ void __launch_bounds__(NTHR, 1)
noteaxis_kernel(const float* __restrict__ feats,
                const float* __restrict__ cond,
                const float* __restrict__ Wout,
                const float* __restrict__ bout,
                float* __restrict__ out)
{
    extern __shared__ float smem[];
    float* sh_w   = smem;                          // 3*8*1024 = 24576 floats
    float* sh_xT  = sh_w + NSTAGE * KC * NG;       // 260 rows
    float* sh_h0T = sh_xT + 260 * ASTR;            // 256 rows (contiguous after xT)
    float* sh_h1T = sh_h0T + NU * ASTR;            // 256 rows (contiguous after h0T)
    unsigned sw_u32 = (unsigned)__cvta_generic_to_shared(sh_w);

    int tid = threadIdx.x;
    int rg  = tid & 3;         // row group: 4 replicas of a unit share a warp
    int ug  = tid >> 2;        // unit index (8 units per warp)
    int rg8 = rg * 8;
    size_t batch0 = (size_t)blockIdx.x * MROWS;

    float* c0g = g_c0 + (size_t)blockIdx.x * (NU * MROWS);
    float* c1g = g_c1 + (size_t)blockIdx.x * (NU * MROWS);

    for (int i = tid; i < 2 * NU * ASTR; i += NTHR) sh_h0T[i] = 0.f;  // h0T + h1T
    // (first gemm chunk's __syncthreads orders the zero-init)

    for (int n = 0; n < NNOTES; n++) {
        // ---- stage x TRANSPOSED: xT[c][r]; coalesced global reads, scattered STS ----
        for (int idx = tid; idx < MROWS * NF; idx += NTHR) {
            int r = idx >> 8;          // NF = 256
            int c = idx & 255;
            sh_xT[c * ASTR + r] = feats[((batch0 + r) * NNOTES + n) * NF + c];
        }
        if (tid < MROWS * 4) {
            int r = tid >> 2, j = tid & 3;
            float v = 0.f;
            if (j < 3 && n > 0) v = cond[((batch0 + r) * NNOTES + (n - 1)) * 3 + j];
            sh_xT[(NF + j) * ASTR + r] = v;   // cols 256..258 = shifted cond, 259 = pad
        }
        // (gemm's first-chunk barrier orders these writes before reads)

        u64 acc[4][4];
        float2 cpre[4];

        // ---- layer 0: gates = [x ++ h0_prev (++ h1 garbage x zero-W)] @ W0 + b0 ----
#pragma unroll
        for (int rp = 0; rp < 4; rp++)
            cpre[rp] = (n == 0) ? make_float2(0.f, 0.f)
                                : *(const float2*)(c0g + ug * 32 + rp * 8 + rg * 2);
        {
            float4 b4 = *(const float4*)(g_b0 + ug * 4);
            u64 bi = pack2(b4.x), bf = pack2(b4.y), bg = pack2(b4.z), bo = pack2(b4.w);
#pragma unroll
            for (int rp = 0; rp < 4; rp++) {
                acc[rp][0] = bi; acc[rp][1] = bf; acc[rp][2] = bg; acc[rp][3] = bo;
            }
        }
        gemm_layer(acc, sh_xT, g_W0, K0TOT / KC, sh_w, sw_u32, tid, rg8, ug);
        cell_update(acc, cpre, c0g, sh_h0T, rg8, rg, ug);

        // ---- layer 1: gates = [h0_new ++ h1_prev] @ W1 + b1 ----
#pragma unroll
        for (int rp = 0; rp < 4; rp++)
            cpre[rp] = (n == 0) ? make_float2(0.f, 0.f)
                                : *(const float2*)(c1g + ug * 32 + rp * 8 + rg * 2);
        {
            float4 b4 = *(const float4*)(g_b1 + ug * 4);
            u64 bi = pack2(b4.x), bf = pack2(b4.y), bg = pack2(b4.z), bo = pack2(b4.w);
#pragma unroll
            for (int rp = 0; rp < 4; rp++) {
                acc[rp][0] = bi; acc[rp][1] = bf; acc[rp][2] = bg; acc[rp][3] = bo;
            }
        }
        gemm_layer(acc, sh_h0T, g_W1, K1TOT / KC, sh_w, sw_u32, tid, rg8, ug);
        cell_update(acc, cpre, c1g, sh_h1T, rg8, rg, ug);

        // ---- output head: out[b,n,ch] = sigmoid?(h1 . Wout[ch] + bout[ch]) ----
        if (tid < MROWS * 3) {
            int r = tid / 3, ch = tid - r * 3;
            const float* wv = Wout + ch * NU;
            float s = bout[ch];
#pragma unroll 8
            for (int u2 = 0; u2 < NU; u2++)
                s += sh_h1T[u2 * ASTR + r] * wv[u2];
            if (ch < 2) s = sigf(s);
            out[((batch0 + r) * NNOTES + n) * 3 + ch] = s;
        }
        // next staging (xT) is disjoint from h0T/h1T; gemm's first barrier gates reuse
    }
}

// ---------------- launch ----------------
extern "C" void kernel_launch(void* const* d_in, const int* in_sizes, int n_in,
                              void* d_out, int out_size)
{
    const float* feats = (const float*)d_in[0];
    const float* cond  = (const float*)d_in[1];
    const float* W_ih0 = (const float*)d_in[2];
    const float* W_hh0 = (const float*)d_in[3];
    const float* b_ih0 = (const float*)d_in[4];
    const float* b_hh0 = (const float*)d_in[5];
    const float* W_ih1 = (const float*)d_in[6];
    const float* W_hh1 = (const float*)d_in[7];
    const float* b_ih1 = (const float*)d_in[8];
    const float* b_hh1 = (const float*)d_in[9];
    const float* W_out = (const float*)d_in[10];
    const float* b_out = (const float*)d_in[11];
    float* out = (float*)d_out;

    prep_kernel<<<264, 256>>>(W_ih0, W_hh0, b_ih0, b_hh0, W_ih1, W_hh1, b_ih1, b_hh1);

    int smem_bytes = (NSTAGE * KC * NG + (260 + 2 * NU) * ASTR) * (int)sizeof(float);
    // = (24576 + 27792) * 4 = 209,472 B  -> 1 CTA/SM
    cudaFuncSetAttribute(noteaxis_kernel,
                         cudaFuncAttributeMaxDynamicSharedMemorySize, smem_bytes);
    noteaxis_kernel<<<NB / MROWS, NTHR, smem_bytes>>>(feats, cond, W_out, b_out, out);
}

// round 14
// speedup vs baseline: 1.0345x; 1.0345x over previous
#include <cuda_runtime.h>

// ---------------- problem constants ----------------
#define NB      4096
#define NNOTES  48
#define NF      256
#define NU      256
#define NG      1024      // 4 * NU (i,f,g,o), interleaved [unit][gate]
#define K0TOT   520       // ih0 (259) + pad(1) + hh0 (256) + pad(4)  -> 40 chunks
#define K1TOT   520       // ih1 (256) + hh1 (256) + pad(8)           -> 40 chunks
#define KC      13        // K rows per pipeline chunk
#define NSTAGE  2
#define CHUNKF4 (KC * NG / 4)   // 3328 float4 per chunk
#define MROWS   32        // batch rows per CTA
#define NTHR    1024
#define ASTR    36        // transposed-A row stride (32 rows + 4 pad)

typedef unsigned long long u64;

// ---------------- device scratch (static, allocation-guard-safe) ----------------
__device__ __align__(16) float g_W0[K0TOT * NG];   // [k][unit*4+gate], pad rows zero
__device__ __align__(16) float g_W1[K1TOT * NG];   // [k][unit*4+gate], pad rows zero
__device__ __align__(16) float g_b0[NG];           // [unit*4+gate]
__device__ __align__(16) float g_b1[NG];
__device__ __align__(16) float g_c0[NB * NU];      // layer-0 cell state (L2-resident)
__device__ __align__(16) float g_c1[NB * NU];      // layer-1 cell state

// ---------------- helpers ----------------
__device__ __forceinline__ u64 pack2(float x) {
    u64 r;
    asm("mov.b64 %0, {%1, %1};" : "=l"(r) : "r"(__float_as_uint(x)));
    return r;
}
__device__ __forceinline__ void fma2(u64& acc, u64 a, u64 b) {
    asm("fma.rn.f32x2 %0, %1, %2, %0;" : "+l"(acc) : "l"(a), "l"(b));
}
__device__ __forceinline__ void unpack2(u64 v, float& lo, float& hi) {
    unsigned int a, b;
    asm("mov.b64 {%0, %1}, %2;" : "=r"(a), "=r"(b) : "l"(v));
    lo = __uint_as_float(a);
    hi = __uint_as_float(b);
}
__device__ __forceinline__ float sigf(float x) {
    return 1.0f / (1.0f + expf(-x));
}
__device__ __forceinline__ void cp16(unsigned dst, const float* src) {
    asm volatile("cp.async.ca.shared.global [%0], [%1], 16;" :: "r"(dst), "l"(src) : "memory");
}
__device__ __forceinline__ void cp_commit() {
    asm volatile("cp.async.commit_group;" ::: "memory");
}
__device__ __forceinline__ void cp_wait0() {
    asm volatile("cp.async.wait_group 0;" ::: "memory");
}

// ---------------- prep: transpose + interleave + concatenate weights ----------------
__global__ void prep_kernel(const float* __restrict__ W_ih0, const float* __restrict__ W_hh0,
                            const float* __restrict__ b_ih0, const float* __restrict__ b_hh0,
                            const float* __restrict__ W_ih1, const float* __restrict__ W_hh1,
                            const float* __restrict__ b_ih1, const float* __restrict__ b_hh1) {
    int tid = blockIdx.x * blockDim.x + threadIdx.x;
    int stride = gridDim.x * blockDim.x;
    for (int i = tid; i < K0TOT * NG; i += stride) {
        int k = i >> 10, j = i & 1023;
        int u = j >> 2, g = j & 3;
        int orow = g * 256 + u;              // original row in [4*NU, K] weight
        float v = 0.f;
        if (k < 259)                  v = W_ih0[orow * 259 + k];
        else if (k >= 260 && k < 516) v = W_hh0[orow * 256 + (k - 260)];
        g_W0[i] = v;                          // rows 259, 516..519 stay zero
    }
    for (int i = tid; i < K1TOT * NG; i += stride) {
        int k = i >> 10, j = i & 1023;
        int u = j >> 2, g = j & 3;
        int orow = g * 256 + u;
        float v = 0.f;
        if (k < 256)       v = W_ih1[orow * 256 + k];
        else if (k < 512)  v = W_hh1[orow * 256 + (k - 256)];
        g_W1[i] = v;                          // rows 512..519 stay zero
    }
    for (int i = tid; i < NG; i += stride) {
        int u = i >> 2, g = i & 3;
        int orow = g * 256 + u;
        g_b0[i] = b_ih0[orow] + b_hh0[orow];
        g_b1[i] = b_ih1[orow] + b_hh1[orow];
    }
}

// ---------------- chunk staging: one KC*NG tile via cp.async ----------------
__device__ __forceinline__ void stage_chunk(unsigned sw_u32, int buf,
                                            const float* __restrict__ Wg, int ci, int tid) {
    unsigned d = sw_u32 + (unsigned)(buf * (KC * NG) + tid * 4) * 4u;
    const float* s = Wg + (size_t)ci * (KC * NG) + tid * 4;
#pragma unroll
    for (int j = 0; j < 4; j++) {
        if (tid + j * NTHR < CHUNKF4)
            cp16(d + (unsigned)(j * NTHR) * 16u, s + j * NTHR * 4);
    }
}

// ---------------- GEMM over one layer (contiguous concatenated A) ----------------
// R12 mapping: thread (rg = tid>>8, ug = tid&255); warp = 32 consecutive ug at
// fixed rg -> A loads are single-address broadcasts (free), W float4 loads are
// 512B contiguous per warp (4 clean wavefronts).
// Race-free 2-stage pipeline: wait0 -> barrier (proves other buffer free) ->
// issue next chunk -> compute current. One barrier per chunk.
__device__ __forceinline__ void gemm_layer(
    u64 (&acc)[4][4],
    const float* A,                      // contiguous [ktot][ASTR]
    const float* __restrict__ Wg, int nchunks,
    const float* sh_w, unsigned sw_u32, int tid, int rg8, int ug)
{
    stage_chunk(sw_u32, 0, Wg, 0, tid);
    cp_commit();
    for (int ci = 0; ci < nchunks; ci++) {
        cp_wait0();              // chunk ci arrived (only in-flight group)
        __syncthreads();         // visible to all; buffer (ci+1)&1 free: its last
                                 // readers (chunk ci-1) passed this barrier too
        if (ci + 1 < nchunks)
            stage_chunk(sw_u32, (ci + 1) & 1, Wg, ci + 1, tid);
        cp_commit();             // LDG of ci+1 hides under compute of ci

        const float* wb = sh_w + (ci & 1) * (KC * NG) + ug * 4;
        const float* ab = A + ci * (KC * ASTR) + rg8;
#pragma unroll
        for (int kk = 0; kk < KC; kk++) {
            ulonglong2 av0 = *(const ulonglong2*)(ab + kk * ASTR);      // bcast
            ulonglong2 av1 = *(const ulonglong2*)(ab + kk * ASTR + 4);  // bcast
            float4 w4 = *(const float4*)(wb + kk * NG);    // gates i,f,g,o
            u64 wi = pack2(w4.x);
            u64 wf = pack2(w4.y);
            u64 wg = pack2(w4.z);
            u64 wo = pack2(w4.w);
            fma2(acc[0][0], av0.x, wi); fma2(acc[1][0], av0.y, wi);
            fma2(acc[2][0], av1.x, wi); fma2(acc[3][0], av1.y, wi);
            fma2(acc[0][1], av0.x, wf); fma2(acc[1][1], av0.y, wf);
            fma2(acc[2][1], av1.x, wf); fma2(acc[3][1], av1.y, wf);
            fma2(acc[0][2], av0.x, wg); fma2(acc[1][2], av0.y, wg);
            fma2(acc[2][2], av1.x, wg); fma2(acc[3][2], av1.y, wg);
            fma2(acc[0][3], av0.x, wo); fma2(acc[1][3], av0.y, wo);
            fma2(acc[2][3], av1.x, wo); fma2(acc[3][3], av1.y, wo);
        }
    }
}

// ---------------- LSTM cell elementwise ----------------
// Thread owns rows rg8..rg8+7 (4 lane-pairs) and unit ug.
// c in prefetched registers -> coalesced STG to L2-resident scratch.
__device__ __forceinline__ void cell_update(
    u64 (&acc)[4][4], const float (&cin)[8], float* __restrict__ cg,
    float* hT, int rg8, int ug)
{
    float hn[8];
#pragma unroll
    for (int rp = 0; rp < 4; rp++) {
        float i0, i1, f0, f1, g0, g1, o0, o1;
        unpack2(acc[rp][0], i0, i1);
        unpack2(acc[rp][1], f0, f1);
        unpack2(acc[rp][2], g0, g1);
        unpack2(acc[rp][3], o0, o1);
        float cn0 = sigf(f0) * cin[2 * rp]     + sigf(i0) * tanhf(g0);
        float cn1 = sigf(f1) * cin[2 * rp + 1] + sigf(i1) * tanhf(g1);
        int r0 = rg8 + 2 * rp;
        cg[r0 * NU + ug]       = cn0;   // coalesced STG.32
        cg[(r0 + 1) * NU + ug] = cn1;
        hn[2 * rp]     = sigf(o0) * tanhf(cn0);
        hn[2 * rp + 1] = sigf(o1) * tanhf(cn1);
    }
    __syncthreads();   // all GEMM readers of old hT are done
    float4* d = (float4*)(hT + ug * ASTR + rg8);
    d[0] = make_float4(hn[0], hn[1], hn[2], hn[3]);
    d[1] = make_float4(hn[4], hn[5], hn[6], hn[7]);
    __syncthreads();   // new hT visible (output head / next GEMM)
}

// ---------------- main persistent kernel ----------------
__global__ void __launch_bounds__(NTHR, 1)
noteaxis_kernel(const float* __restrict__ feats,
                const float* __restrict__ cond,
                const float* __restrict__ Wout,
                const float* __restrict__ bout,
                float* __restrict__ out)
{
    extern __shared__ float smem[];
    float* sh_w   = smem;                          // 2*13*1024 = 26624 floats
    float* sh_xT  = sh_w + NSTAGE * KC * NG;       // 260 rows
    float* sh_h0T = sh_xT + 260 * ASTR;            // 256 rows (contiguous after xT)
    float* sh_h1T = sh_h0T + NU * ASTR;            // 256 rows + 8 zero pad rows
    unsigned sw_u32 = (unsigned)__cvta_generic_to_shared(sh_w);

    int tid = threadIdx.x;
    int rg  = tid >> 8;        // 0..3, warp-uniform
    int ug  = tid & 255;       // unit index
    int rg8 = rg * 8;
    size_t batch0 = (size_t)blockIdx.x * MROWS;

    float* c0g = g_c0 + batch0 * NU;
    float* c1g = g_c1 + batch0 * NU;

    // zero h0T, h1T and the 8 pad rows after h1T (garbage x zero-W must stay finite)
    for (int i = tid; i < (2 * NU + 8) * ASTR; i += NTHR) sh_h0T[i] = 0.f;
    // (first gemm chunk's __syncthreads orders the zero-init)

    for (int n = 0; n < NNOTES; n++) {
        // ---- stage x TRANSPOSED: xT[c][r]; coalesced global reads, scattered STS ----
        for (int idx = tid; idx < MROWS * NF; idx += NTHR) {
            int r = idx >> 8;          // NF = 256
            int c = idx & 255;
            sh_xT[c * ASTR + r] = feats[((batch0 + r) * NNOTES + n) * NF + c];
        }
        if (tid < MROWS * 4) {
            int r = tid >> 2, j = tid & 3;
            float v = 0.f;
            if (j < 3 && n > 0) v = cond[((batch0 + r) * NNOTES + (n - 1)) * 3 + j];
            sh_xT[(NF + j) * ASTR + r] = v;   // cols 256..258 = shifted cond, 259 = pad
        }
        // (gemm's first-chunk barrier orders these writes before reads)

        u64 acc[4][4];
        float cpre[8];

        // ---- layer 0: gates = [x ++ h0_prev (++ h1 data x zero-W)] @ W0 + b0 ----
#pragma unroll
        for (int rp = 0; rp < 8; rp++)
            cpre[rp] = (n == 0) ? 0.f : c0g[(rg8 + rp) * NU + ug];   // hidden by GEMM
        {
            float4 b4 = *(const float4*)(g_b0 + ug * 4);
            u64 bi = pack2(b4.x), bf = pack2(b4.y), bg = pack2(b4.z), bo = pack2(b4.w);
#pragma unroll
            for (int rp = 0; rp < 4; rp++) {
                acc[rp][0] = bi; acc[rp][1] = bf; acc[rp][2] = bg; acc[rp][3] = bo;
            }
        }
        gemm_layer(acc, sh_xT, g_W0, K0TOT / KC, sh_w, sw_u32, tid, rg8, ug);
        cell_update(acc, cpre, c0g, sh_h0T, rg8, ug);

        // ---- layer 1: gates = [h0_new ++ h1_prev (++ zero pad)] @ W1 + b1 ----
#pragma unroll
        for (int rp = 0; rp < 8; rp++)
            cpre[rp] = (n == 0) ? 0.f : c1g[(rg8 + rp) * NU + ug];
        {
            float4 b4 = *(const float4*)(g_b1 + ug * 4);
            u64 bi = pack2(b4.x), bf = pack2(b4.y), bg = pack2(b4.z), bo = pack2(b4.w);
#pragma unroll
            for (int rp = 0; rp < 4; rp++) {
                acc[rp][0] = bi; acc[rp][1] = bf; acc[rp][2] = bg; acc[rp][3] = bo;
            }
        }
        gemm_layer(acc, sh_h0T, g_W1, K1TOT / KC, sh_w, sw_u32, tid, rg8, ug);
        cell_update(acc, cpre, c1g, sh_h1T, rg8, ug);

        // ---- output head: out[b,n,ch] = sigmoid?(h1 . Wout[ch] + bout[ch]) ----
        if (tid < MROWS * 3) {
            int r = tid / 3, ch = tid - r * 3;
            const float* wv = Wout + ch * NU;
            float s = bout[ch];
#pragma unroll 8
            for (int u2 = 0; u2 < NU; u2++)
                s += sh_h1T[u2 * ASTR + r] * wv[u2];
            if (ch < 2) s = sigf(s);
            out[((batch0 + r) * NNOTES + n) * 3 + ch] = s;
        }
        // next staging (xT) is disjoint from h0T/h1T; gemm's first barrier gates reuse
    }
}

// ---------------- launch ----------------
extern "C" void kernel_launch(void* const* d_in, const int* in_sizes, int n_in,
                              void* d_out, int out_size)
{
    const float* feats = (const float*)d_in[0];
    const float* cond  = (const float*)d_in[1];
    const float* W_ih0 = (const float*)d_in[2];
    const float* W_hh0 = (const float*)d_in[3];
    const float* b_ih0 = (const float*)d_in[4];
    const float* b_hh0 = (const float*)d_in[5];
    const float* W_ih1 = (const float*)d_in[6];
    const float* W_hh1 = (const float*)d_in[7];
    const float* b_ih1 = (const float*)d_in[8];
    const float* b_hh1 = (const float*)d_in[9];
    const float* W_out = (const float*)d_in[10];
    const float* b_out = (const float*)d_in[11];
    float* out = (float*)d_out;

    prep_kernel<<<264, 256>>>(W_ih0, W_hh0, b_ih0, b_hh0, W_ih1, W_hh1, b_ih1, b_hh1);

    int smem_bytes = (NSTAGE * KC * NG + (260 + 2 * NU + 8) * ASTR) * (int)sizeof(float);
    // = (26624 + 28080) * 4 = 218,816 B  -> 1 CTA/SM
    cudaFuncSetAttribute(noteaxis_kernel,
                         cudaFuncAttributeMaxDynamicSharedMemorySize, smem_bytes);
    noteaxis_kernel<<<NB / MROWS, NTHR, smem_bytes>>>(feats, cond, W_out, b_out, out);
}

// round 15
// speedup vs baseline: 1.0906x; 1.0543x over previous
#include <cuda_runtime.h>

// ---------------- problem constants ----------------
#define NB      4096
#define NNOTES  48
#define NF      256
#define NU      256
#define NG      1024      // 4 * NU (i,f,g,o), interleaved [unit][gate]
#define K0TOT   520       // ih0 (259) + pad(1) + hh0 (256) + pad(4)  -> 40 chunks
#define K1TOT   520       // ih1 (256) + hh1 (256) + pad(8)           -> 40 chunks
#define KC      13        // K rows per pipeline chunk
#define NSTAGE  2
#define CHUNKF4 (KC * NG / 4)   // 3328 float4 per chunk
#define MROWS   32        // batch rows per CTA
#define NTHR    1024
#define ASTR    36        // transposed-A row stride (32 rows + 4 pad)

typedef unsigned long long u64;

// ---------------- device scratch (static, allocation-guard-safe) ----------------
__device__ __align__(16) float g_W0[K0TOT * NG];   // [k][unit*4+gate], pad rows zero
__device__ __align__(16) float g_W1[K1TOT * NG];   // [k][unit*4+gate], pad rows zero
__device__ __align__(16) float g_b0[NG];           // [unit*4+gate]
__device__ __align__(16) float g_b1[NG];
__device__ __align__(16) float g_c0[NB * NU];      // layer-0 cell state (L2-resident)
__device__ __align__(16) float g_c1[NB * NU];      // layer-1 cell state

// ---------------- helpers ----------------
__device__ __forceinline__ u64 pack2(float x) {
    u64 r;
    asm("mov.b64 %0, {%1, %1};" : "=l"(r) : "r"(__float_as_uint(x)));
    return r;
}
__device__ __forceinline__ void fma2(u64& acc, u64 a, u64 b) {
    asm("fma.rn.f32x2 %0, %1, %2, %0;" : "+l"(acc) : "l"(a), "l"(b));
}
__device__ __forceinline__ void unpack2(u64 v, float& lo, float& hi) {
    unsigned int a, b;
    asm("mov.b64 {%0, %1}, %2;" : "=r"(a), "=r"(b) : "l"(v));
    lo = __uint_as_float(a);
    hi = __uint_as_float(b);
}
__device__ __forceinline__ float sigf(float x) {
    return 1.0f / (1.0f + expf(-x));
}
__device__ __forceinline__ void cp16(unsigned dst, const float* src) {
    asm volatile("cp.async.ca.shared.global [%0], [%1], 16;" :: "r"(dst), "l"(src) : "memory");
}
__device__ __forceinline__ void cp_commit() {
    asm volatile("cp.async.commit_group;" ::: "memory");
}
__device__ __forceinline__ void cp_wait0() {
    asm volatile("cp.async.wait_group 0;" ::: "memory");
}

// ---------------- prep: transpose + interleave + concatenate weights ----------------
__global__ void prep_kernel(const float* __restrict__ W_ih0, const float* __restrict__ W_hh0,
                            const float* __restrict__ b_ih0, const float* __restrict__ b_hh0,
                            const float* __restrict__ W_ih1, const float* __restrict__ W_hh1,
                            const float* __restrict__ b_ih1, const float* __restrict__ b_hh1) {
    int tid = blockIdx.x * blockDim.x + threadIdx.x;
    int stride = gridDim.x * blockDim.x;
    for (int i = tid; i < K0TOT * NG; i += stride) {
        int k = i >> 10, j = i & 1023;
        int u = j >> 2, g = j & 3;
        int orow = g * 256 + u;              // original row in [4*NU, K] weight
        float v = 0.f;
        if (k < 259)                  v = W_ih0[orow * 259 + k];
        else if (k >= 260 && k < 516) v = W_hh0[orow * 256 + (k - 260)];
        g_W0[i] = v;                          // rows 259, 516..519 stay zero
    }
    for (int i = tid; i < K1TOT * NG; i += stride) {
        int k = i >> 10, j = i & 1023;
        int u = j >> 2, g = j & 3;
        int orow = g * 256 + u;
        float v = 0.f;
        if (k < 256)       v = W_ih1[orow * 256 + k];
        else if (k < 512)  v = W_hh1[orow * 256 + (k - 256)];
        g_W1[i] = v;                          // rows 512..519 stay zero
    }
    for (int i = tid; i < NG; i += stride) {
        int u = i >> 2, g = i & 3;
        int orow = g * 256 + u;
        g_b0[i] = b_ih0[orow] + b_hh0[orow];
        g_b1[i] = b_ih1[orow] + b_hh1[orow];
    }
}

// ---------------- chunk staging: one KC*NG tile via cp.async ----------------
__device__ __forceinline__ void stage_chunk(unsigned sw_u32, int buf,
                                            const float* __restrict__ Wg, int ci, int tid) {
    unsigned d = sw_u32 + (unsigned)(buf * (KC * NG) + tid * 4) * 4u;
    const float* s = Wg + (size_t)ci * (KC * NG) + tid * 4;
#pragma unroll
    for (int j = 0; j < 4; j++) {
        if (tid + j * NTHR < CHUNKF4)
            cp16(d + (unsigned)(j * NTHR) * 16u, s + j * NTHR * 4);
    }
}

// ---------------- GEMM over one layer (contiguous concatenated A) ----------------
// R12 mapping: thread (rg = tid>>8, ug = tid&255); warp = 32 consecutive ug at
// fixed rg -> A loads are single-address broadcasts (free), W float4 loads are
// 512B contiguous per warp (4 clean wavefronts).
// Race-free 2-stage pipeline: wait0 -> barrier (proves other buffer free) ->
// issue next chunk -> compute current. One barrier per chunk.
__device__ __forceinline__ void gemm_layer(
    u64 (&acc)[4][4],
    const float* A,                      // contiguous [ktot][ASTR]
    const float* __restrict__ Wg, int nchunks,
    const float* sh_w, unsigned sw_u32, int tid, int rg8, int ug)
{
    stage_chunk(sw_u32, 0, Wg, 0, tid);
    cp_commit();
    for (int ci = 0; ci < nchunks; ci++) {
        cp_wait0();              // chunk ci arrived (only in-flight group)
        __syncthreads();         // visible to all; buffer (ci+1)&1 free: its last
                                 // readers (chunk ci-1) passed this barrier too
        if (ci + 1 < nchunks)
            stage_chunk(sw_u32, (ci + 1) & 1, Wg, ci + 1, tid);
        cp_commit();             // LDG of ci+1 hides under compute of ci

        const float* wb = sh_w + (ci & 1) * (KC * NG) + ug * 4;
        const float* ab = A + ci * (KC * ASTR) + rg8;
#pragma unroll
        for (int kk = 0; kk < KC; kk++) {
            ulonglong2 av0 = *(const ulonglong2*)(ab + kk * ASTR);      // bcast
            ulonglong2 av1 = *(const ulonglong2*)(ab + kk * ASTR + 4);  // bcast
            float4 w4 = *(const float4*)(wb + kk * NG);    // gates i,f,g,o
            u64 wi = pack2(w4.x);
            u64 wf = pack2(w4.y);
            u64 wg = pack2(w4.z);
            u64 wo = pack2(w4.w);
            fma2(acc[0][0], av0.x, wi); fma2(acc[1][0], av0.y, wi);
            fma2(acc[2][0], av1.x, wi); fma2(acc[3][0], av1.y, wi);
            fma2(acc[0][1], av0.x, wf); fma2(acc[1][1], av0.y, wf);
            fma2(acc[2][1], av1.x, wf); fma2(acc[3][1], av1.y, wf);
            fma2(acc[0][2], av0.x, wg); fma2(acc[1][2], av0.y, wg);
            fma2(acc[2][2], av1.x, wg); fma2(acc[3][2], av1.y, wg);
            fma2(acc[0][3], av0.x, wo); fma2(acc[1][3], av0.y, wo);
            fma2(acc[2][3], av1.x, wo); fma2(acc[3][3], av1.y, wo);
        }
    }
}

// ---------------- LSTM cell elementwise ----------------
// Thread owns rows rg8..rg8+7 (4 lane-pairs) and unit ug.
// c in prefetched registers -> coalesced STG to L2-resident scratch.
__device__ __forceinline__ void cell_update(
    u64 (&acc)[4][4], const float (&cin)[8], float* __restrict__ cg,
    float* hT, int rg8, int ug)
{
    float hn[8];
#pragma unroll
    for (int rp = 0; rp < 4; rp++) {
        float i0, i1, f0, f1, g0, g1, o0, o1;
        unpack2(acc[rp][0], i0, i1);
        unpack2(acc[rp][1], f0, f1);
        unpack2(acc[rp][2], g0, g1);
        unpack2(acc[rp][3], o0, o1);
        float cn0 = sigf(f0) * cin[2 * rp]     + sigf(i0) * tanhf(g0);
        float cn1 = sigf(f1) * cin[2 * rp + 1] + sigf(i1) * tanhf(g1);
        int r0 = rg8 + 2 * rp;
        cg[r0 * NU + ug]       = cn0;   // coalesced STG.32
        cg[(r0 + 1) * NU + ug] = cn1;
        hn[2 * rp]     = sigf(o0) * tanhf(cn0);
        hn[2 * rp + 1] = sigf(o1) * tanhf(cn1);
    }
    __syncthreads();   // all GEMM readers of old hT are done
    float4* d = (float4*)(hT + ug * ASTR + rg8);
    d[0] = make_float4(hn[0], hn[1], hn[2], hn[3]);
    d[1] = make_float4(hn[4], hn[5], hn[6], hn[7]);
    __syncthreads();   // new hT visible (output head / next GEMM)
}

// ---------------- main persistent kernel ----------------
__global__ void __launch_bounds__(NTHR, 1)
noteaxis_kernel(const float* __restrict__ feats,
                const float* __restrict__ cond,
                const float* __restrict__ Wout,
                const float* __restrict__ bout,
                float* __restrict__ out)
{
    extern __shared__ float smem[];
    float* sh_w   = smem;                          // 2*13*1024 = 26624 floats
    float* sh_xT  = sh_w + NSTAGE * KC * NG;       // 260 rows
    float* sh_h0T = sh_xT + 260 * ASTR;            // 256 rows (contiguous after xT)
    float* sh_h1T = sh_h0T + NU * ASTR;            // 256 rows + 8 zero pad rows
    unsigned sw_u32 = (unsigned)__cvta_generic_to_shared(sh_w);

    int tid = threadIdx.x;
    int rg  = tid >> 8;        // 0..3, warp-uniform
    int ug  = tid & 255;       // unit index
    int rg8 = rg * 8;
    size_t batch0 = (size_t)blockIdx.x * MROWS;

    float* c0g = g_c0 + batch0 * NU;
    float* c1g = g_c1 + batch0 * NU;

    // zero h0T, h1T and the 8 pad rows after h1T (garbage x zero-W must stay finite)
    for (int i = tid; i < (2 * NU + 8) * ASTR; i += NTHR) sh_h0T[i] = 0.f;
    // (first gemm chunk's __syncthreads orders the zero-init)

    for (int n = 0; n < NNOTES; n++) {
        // ---- stage x TRANSPOSED: xT[c][r]; coalesced global reads, scattered STS ----
        for (int idx = tid; idx < MROWS * NF; idx += NTHR) {
            int r = idx >> 8;          // NF = 256
            int c = idx & 255;
            sh_xT[c * ASTR + r] = feats[((batch0 + r) * NNOTES + n) * NF + c];
        }
        if (tid < MROWS * 4) {
            int r = tid >> 2, j = tid & 3;
            float v = 0.f;
            if (j < 3 && n > 0) v = cond[((batch0 + r) * NNOTES + (n - 1)) * 3 + j];
            sh_xT[(NF + j) * ASTR + r] = v;   // cols 256..258 = shifted cond, 259 = pad
        }
        // (gemm's first-chunk barrier orders these writes before reads)

        u64 acc[4][4];
        float cpre[8];

        // ---- layer 0: gates = [x ++ h0_prev (++ h1 data x zero-W)] @ W0 + b0 ----
#pragma unroll
        for (int rp = 0; rp < 8; rp++)
            cpre[rp] = (n == 0) ? 0.f : c0g[(rg8 + rp) * NU + ug];   // hidden by GEMM
        {
            float4 b4 = *(const float4*)(g_b0 + ug * 4);
            u64 bi = pack2(b4.x), bf = pack2(b4.y), bg = pack2(b4.z), bo = pack2(b4.w);
#pragma unroll
            for (int rp = 0; rp < 4; rp++) {
                acc[rp][0] = bi; acc[rp][1] = bf; acc[rp][2] = bg; acc[rp][3] = bo;
            }
        }
        gemm_layer(acc, sh_xT, g_W0, K0TOT / KC, sh_w, sw_u32, tid, rg8, ug);
        cell_update(acc, cpre, c0g, sh_h0T, rg8, ug);

        // ---- layer 1: gates = [h0_new ++ h1_prev (++ zero pad)] @ W1 + b1 ----
#pragma unroll
        for (int rp = 0; rp < 8; rp++)
            cpre[rp] = (n == 0) ? 0.f : c1g[(rg8 + rp) * NU + ug];
        {
            float4 b4 = *(const float4*)(g_b1 + ug * 4);
            u64 bi = pack2(b4.x), bf = pack2(b4.y), bg = pack2(b4.z), bo = pack2(b4.w);
#pragma unroll
            for (int rp = 0; rp < 4; rp++) {
                acc[rp][0] = bi; acc[rp][1] = bf; acc[rp][2] = bg; acc[rp][3] = bo;
            }
        }
        gemm_layer(acc, sh_h0T, g_W1, K1TOT / KC, sh_w, sw_u32, tid, rg8, ug);
        cell_update(acc, cpre, c1g, sh_h1T, rg8, ug);

        // ---- output head: out[b,n,ch] = sigmoid?(h1 . Wout[ch] + bout[ch]) ----
        if (tid < MROWS * 3) {
            int r = tid / 3, ch = tid - r * 3;
            const float* wv = Wout + ch * NU;
            float s = bout[ch];
#pragma unroll 8
            for (int u2 = 0; u2 < NU; u2++)
                s += sh_h1T[u2 * ASTR + r] * wv[u2];
            if (ch < 2) s = sigf(s);
            out[((batch0 + r) * NNOTES + n) * 3 + ch] = s;
        }
        // next staging (xT) is disjoint from h0T/h1T; gemm's first barrier gates reuse
    }
}

// ---------------- launch ----------------
extern "C" void kernel_launch(void* const* d_in, const int* in_sizes, int n_in,
                              void* d_out, int out_size)
{
    const float* feats = (const float*)d_in[0];
    const float* cond  = (const float*)d_in[1];
    const float* W_ih0 = (const float*)d_in[2];
    const float* W_hh0 = (const float*)d_in[3];
    const float* b_ih0 = (const float*)d_in[4];
    const float* b_hh0 = (const float*)d_in[5];
    const float* W_ih1 = (const float*)d_in[6];
    const float* W_hh1 = (const float*)d_in[7];
    const float* b_ih1 = (const float*)d_in[8];
    const float* b_hh1 = (const float*)d_in[9];
    const float* W_out = (const float*)d_in[10];
    const float* b_out = (const float*)d_in[11];
    float* out = (float*)d_out;

    prep_kernel<<<264, 256>>>(W_ih0, W_hh0, b_ih0, b_hh0, W_ih1, W_hh1, b_ih1, b_hh1);

    int smem_bytes = (NSTAGE * KC * NG + (260 + 2 * NU + 8) * ASTR) * (int)sizeof(float);
    // = (26624 + 28080) * 4 = 218,816 B  -> 1 CTA/SM
    cudaFuncSetAttribute(noteaxis_kernel,
                         cudaFuncAttributeMaxDynamicSharedMemorySize, smem_bytes);
    noteaxis_kernel<<<NB / MROWS, NTHR, smem_bytes>>>(feats, cond, W_out, b_out, out);
}

// round 16
// speedup vs baseline: 1.2232x; 1.1216x over previous
#include <cuda_runtime.h>

// ---------------- problem constants ----------------
#define NB      4096
#define NNOTES  48
#define NF      256
#define NU      256
#define NG      1024      // 4 * NU (i,f,g,o), interleaved [unit][gate]
#define K0TOT   520       // ih0 (259) + pad(1) + hh0 (256) + pad(4)
#define K1TOT   520       // ih1 (256) + hh1 (256) + pad(8)
#define MROWS   32        // batch rows per CTA
#define NTHR    1024
#define ASTR    36        // transposed-A row stride (32 rows + 4 pad)

typedef unsigned long long u64;

// ---------------- device scratch (static, allocation-guard-safe) ----------------
__device__ __align__(16) float g_W0[K0TOT * NG];   // [k][unit*4+gate], pad rows zero
__device__ __align__(16) float g_W1[K1TOT * NG];   // [k][unit*4+gate], pad rows zero
__device__ __align__(16) float g_b0[NG];           // [unit*4+gate]
__device__ __align__(16) float g_b1[NG];
__device__ __align__(16) float g_c0[NB * NU];      // layer-0 cell state (L2-resident)
__device__ __align__(16) float g_c1[NB * NU];      // layer-1 cell state

// ---------------- helpers ----------------
__device__ __forceinline__ u64 pack2(float x) {
    u64 r;
    asm("mov.b64 %0, {%1, %1};" : "=l"(r) : "r"(__float_as_uint(x)));
    return r;
}
__device__ __forceinline__ void fma2(u64& acc, u64 a, u64 b) {
    asm("fma.rn.f32x2 %0, %1, %2, %0;" : "+l"(acc) : "l"(a), "l"(b));
}
__device__ __forceinline__ void unpack2(u64 v, float& lo, float& hi) {
    unsigned int a, b;
    asm("mov.b64 {%0, %1}, %2;" : "=r"(a), "=r"(b) : "l"(v));
    lo = __uint_as_float(a);
    hi = __uint_as_float(b);
}
__device__ __forceinline__ float sigf(float x) {
    return 1.0f / (1.0f + expf(-x));
}

// ---------------- prep: transpose + interleave + concatenate weights ----------------
__global__ void prep_kernel(const float* __restrict__ W_ih0, const float* __restrict__ W_hh0,
                            const float* __restrict__ b_ih0, const float* __restrict__ b_hh0,
                            const float* __restrict__ W_ih1, const float* __restrict__ W_hh1,
                            const float* __restrict__ b_ih1, const float* __restrict__ b_hh1) {
    int tid = blockIdx.x * blockDim.x + threadIdx.x;
    int stride = gridDim.x * blockDim.x;
    for (int i = tid; i < K0TOT * NG; i += stride) {
        int k = i >> 10, j = i & 1023;
        int u = j >> 2, g = j & 3;
        int orow = g * 256 + u;              // original row in [4*NU, K] weight
        float v = 0.f;
        if (k < 259)                  v = W_ih0[orow * 259 + k];
        else if (k >= 260 && k < 516) v = W_hh0[orow * 256 + (k - 260)];
        g_W0[i] = v;                          // rows 259, 516..519 stay zero
    }
    for (int i = tid; i < K1TOT * NG; i += stride) {
        int k = i >> 10, j = i & 1023;
        int u = j >> 2, g = j & 3;
        int orow = g * 256 + u;
        float v = 0.f;
        if (k < 256)       v = W_ih1[orow * 256 + k];
        else if (k < 512)  v = W_hh1[orow * 256 + (k - 256)];
        g_W1[i] = v;                          // rows 512..519 stay zero
    }
    for (int i = tid; i < NG; i += stride) {
        int u = i >> 2, g = i & 3;
        int orow = g * 256 + u;
        g_b0[i] = b_ih0[orow] + b_hh0[orow];
        g_b1[i] = b_ih1[orow] + b_hh1[orow];
    }
}

// ---------------- GEMM over one layer: W direct global->register ----------------
// Thread (rg = tid>>8, ug = tid&255): rows rg*8..rg*8+7 (f32x2 lanes = row pairs),
// unit ug, all 4 gates. A transposed in smem (broadcast LDS); W loaded straight
// from global as one LDG.128 per k per thread. The 4 rg-replica warps touch the
// same lines back-to-back -> L1 serves the redundancy; shared crossbar carries
// only A broadcasts. NO barriers inside the loop: warps drift and hide latency.
__device__ __forceinline__ void gemm_layer(
    u64 (&acc)[4][4],
    const float* A,                      // contiguous [520][ASTR] in smem
    const float* __restrict__ Wg,        // [ktot][NG] in global
    int ktot, int rg8, int ug)
{
    const float4* __restrict__ wp = (const float4*)(Wg + ug * 4);
    for (int k0 = 0; k0 < ktot; k0 += 4) {
        // batch 4 independent LDG.128 (front-loaded MLP for L1/L2 latency)
        float4 w0 = __ldg(wp + (size_t)(k0 + 0) * (NG / 4));
        float4 w1 = __ldg(wp + (size_t)(k0 + 1) * (NG / 4));
        float4 w2 = __ldg(wp + (size_t)(k0 + 2) * (NG / 4));
        float4 w3 = __ldg(wp + (size_t)(k0 + 3) * (NG / 4));
        const float* ab = A + k0 * ASTR + rg8;
#pragma unroll
        for (int kk = 0; kk < 4; kk++) {
            float4 w4 = (kk == 0) ? w0 : (kk == 1) ? w1 : (kk == 2) ? w2 : w3;
            ulonglong2 av0 = *(const ulonglong2*)(ab + kk * ASTR);      // bcast LDS.128
            ulonglong2 av1 = *(const ulonglong2*)(ab + kk * ASTR + 4);  // bcast LDS.128
            u64 wi = pack2(w4.x);
            u64 wf = pack2(w4.y);
            u64 wg = pack2(w4.z);
            u64 wo = pack2(w4.w);
            fma2(acc[0][0], av0.x, wi); fma2(acc[1][0], av0.y, wi);
            fma2(acc[2][0], av1.x, wi); fma2(acc[3][0], av1.y, wi);
            fma2(acc[0][1], av0.x, wf); fma2(acc[1][1], av0.y, wf);
            fma2(acc[2][1], av1.x, wf); fma2(acc[3][1], av1.y, wf);
            fma2(acc[0][2], av0.x, wg); fma2(acc[1][2], av0.y, wg);
            fma2(acc[2][2], av1.x, wg); fma2(acc[3][2], av1.y, wg);
            fma2(acc[0][3], av0.x, wo); fma2(acc[1][3], av0.y, wo);
            fma2(acc[2][3], av1.x, wo); fma2(acc[3][3], av1.y, wo);
        }
    }
}

// ---------------- LSTM cell elementwise ----------------
// Thread owns rows rg8..rg8+7 (4 lane-pairs) and unit ug.
// c in prefetched registers -> coalesced STG to L2-resident scratch.
__device__ __forceinline__ void cell_update(
    u64 (&acc)[4][4], const float (&cin)[8], float* __restrict__ cg,
    float* hT, int rg8, int ug)
{
    float hn[8];
#pragma unroll
    for (int rp = 0; rp < 4; rp++) {
        float i0, i1, f0, f1, g0, g1, o0, o1;
        unpack2(acc[rp][0], i0, i1);
        unpack2(acc[rp][1], f0, f1);
        unpack2(acc[rp][2], g0, g1);
        unpack2(acc[rp][3], o0, o1);
        float cn0 = sigf(f0) * cin[2 * rp]     + sigf(i0) * tanhf(g0);
        float cn1 = sigf(f1) * cin[2 * rp + 1] + sigf(i1) * tanhf(g1);
        int r0 = rg8 + 2 * rp;
        cg[r0 * NU + ug]       = cn0;   // coalesced STG.32
        cg[(r0 + 1) * NU + ug] = cn1;
        hn[2 * rp]     = sigf(o0) * tanhf(cn0);
        hn[2 * rp + 1] = sigf(o1) * tanhf(cn1);
    }
    __syncthreads();   // all GEMM readers of old hT are done
    float4* d = (float4*)(hT + ug * ASTR + rg8);
    d[0] = make_float4(hn[0], hn[1], hn[2], hn[3]);
    d[1] = make_float4(hn[4], hn[5], hn[6], hn[7]);
    __syncthreads();   // new hT visible (output head / next GEMM)
}

// ---------------- main persistent kernel ----------------
__global__ void __launch_bounds__(NTHR, 1)
noteaxis_kernel(const float* __restrict__ feats,
                const float* __restrict__ cond,
                const float* __restrict__ Wout,
                const float* __restrict__ bout,
                float* __restrict__ out)
{
    extern __shared__ float smem[];
    float* sh_xT  = smem;                 // 260 rows
    float* sh_h0T = sh_xT + 260 * ASTR;   // 256 rows (contiguous after xT)
    float* sh_h1T = sh_h0T + NU * ASTR;   // 256 rows + 8 zero pad rows

    int tid = threadIdx.x;
    int rg  = tid >> 8;        // 0..3, warp-uniform
    int ug  = tid & 255;       // unit index
    int rg8 = rg * 8;
    size_t batch0 = (size_t)blockIdx.x * MROWS;

    float* c0g = g_c0 + batch0 * NU;
    float* c1g = g_c1 + batch0 * NU;

    // zero h0T, h1T and the 8 pad rows after h1T (pad x zero-W must stay finite)
    for (int i = tid; i < (2 * NU + 8) * ASTR; i += NTHR) sh_h0T[i] = 0.f;
    __syncthreads();

    for (int n = 0; n < NNOTES; n++) {
        // ---- stage x TRANSPOSED: xT[c][r]; coalesced global reads, scattered STS ----
        for (int idx = tid; idx < MROWS * NF; idx += NTHR) {
            int r = idx >> 8;          // NF = 256
            int c = idx & 255;
            sh_xT[c * ASTR + r] = feats[((batch0 + r) * NNOTES + n) * NF + c];
        }
        if (tid < MROWS * 4) {
            int r = tid >> 2, j = tid & 3;
            float v = 0.f;
            if (j < 3 && n > 0) v = cond[((batch0 + r) * NNOTES + (n - 1)) * 3 + j];
            sh_xT[(NF + j) * ASTR + r] = v;   // cols 256..258 = shifted cond, 259 = pad
        }
        __syncthreads();   // x tile visible before layer-0 GEMM reads it

        u64 acc[4][4];
        float cpre[8];

        // ---- layer 0: gates = [x ++ h0_prev (++ h1 data x zero-W)] @ W0 + b0 ----
#pragma unroll
        for (int rp = 0; rp < 8; rp++)
            cpre[rp] = (n == 0) ? 0.f : c0g[(rg8 + rp) * NU + ug];   // hidden by GEMM
        {
            float4 b4 = *(const float4*)(g_b0 + ug * 4);
            u64 bi = pack2(b4.x), bf = pack2(b4.y), bg = pack2(b4.z), bo = pack2(b4.w);
#pragma unroll
            for (int rp = 0; rp < 4; rp++) {
                acc[rp][0] = bi; acc[rp][1] = bf; acc[rp][2] = bg; acc[rp][3] = bo;
            }
        }
        gemm_layer(acc, sh_xT, g_W0, K0TOT, rg8, ug);
        cell_update(acc, cpre, c0g, sh_h0T, rg8, ug);

        // ---- layer 1: gates = [h0_new ++ h1_prev (++ zero pad)] @ W1 + b1 ----
#pragma unroll
        for (int rp = 0; rp < 8; rp++)
            cpre[rp] = (n == 0) ? 0.f : c1g[(rg8 + rp) * NU + ug];
        {
            float4 b4 = *(const float4*)(g_b1 + ug * 4);
            u64 bi = pack2(b4.x), bf = pack2(b4.y), bg = pack2(b4.z), bo = pack2(b4.w);
#pragma unroll
            for (int rp = 0; rp < 4; rp++) {
                acc[rp][0] = bi; acc[rp][1] = bf; acc[rp][2] = bg; acc[rp][3] = bo;
            }
        }
        gemm_layer(acc, sh_h0T, g_W1, K1TOT, rg8, ug);
        cell_update(acc, cpre, c1g, sh_h1T, rg8, ug);

        // ---- output head: out[b,n,ch] = sigmoid?(h1 . Wout[ch] + bout[ch]) ----
        if (tid < MROWS * 3) {
            int r = tid / 3, ch = tid - r * 3;
            const float* wv = Wout + ch * NU;
            float s = bout[ch];
#pragma unroll 8
            for (int u2 = 0; u2 < NU; u2++)
                s += sh_h1T[u2 * ASTR + r] * wv[u2];
            if (ch < 2) s = sigf(s);
            out[((batch0 + r) * NNOTES + n) * 3 + ch] = s;
        }
        // next x staging is fenced by the barrier at the top of the loop body
        __syncthreads();   // h1T readers (output head) done before next overwrite
    }
}

// ---------------- launch ----------------
extern "C" void kernel_launch(void* const* d_in, const int* in_sizes, int n_in,
                              void* d_out, int out_size)
{
    const float* feats = (const float*)d_in[0];
    const float* cond  = (const float*)d_in[1];
    const float* W_ih0 = (const float*)d_in[2];
    const float* W_hh0 = (const float*)d_in[3];
    const float* b_ih0 = (const float*)d_in[4];
    const float* b_hh0 = (const float*)d_in[5];
    const float* W_ih1 = (const float*)d_in[6];
    const float* W_hh1 = (const float*)d_in[7];
    const float* b_ih1 = (const float*)d_in[8];
    const float* b_hh1 = (const float*)d_in[9];
    const float* W_out = (const float*)d_in[10];
    const float* b_out = (const float*)d_in[11];
    float* out = (float*)d_out;

    prep_kernel<<<264, 256>>>(W_ih0, W_hh0, b_ih0, b_hh0, W_ih1, W_hh1, b_ih1, b_hh1);

    int smem_bytes = (260 * ASTR + (2 * NU + 8) * ASTR) * (int)sizeof(float);
    // = 780 * 36 * 4 = 112,320 B
    cudaFuncSetAttribute(noteaxis_kernel,
                         cudaFuncAttributeMaxDynamicSharedMemorySize, smem_bytes);
    noteaxis_kernel<<<NB / MROWS, NTHR, smem_bytes>>>(feats, cond, W_out, b_out, out);
}